// round 11
// baseline (speedup 1.0000x reference)
#include <cuda_runtime.h>
#include <cstdint>

// Problem constants (match reference)
#define N_SRC   20000
#define N_DST   20000
#define N_NODES 40000
#define E_TOT   320000
#define NHEAD   8
#define HDIM    16
#define FDIM    128
#define TEM     0.7f
#define NEG_SLOPE 0.2f
#define E_SHIFT 10.0f   // constant softmax shift; cancels in alpha = w / sum(w)

// Scratch (device globals; zero-initialized at module load; every launch
// restores them to zero where required -> deterministic across graph replays)
__device__ float g_z[N_NODES * FDIM];        // 20.5 MB, L2-resident
__device__ float g_el[N_NODES * NHEAD];
__device__ float g_er[N_NODES * NHEAD];
__device__ int   g_counts[N_DST];            // zeroed by scan after reading
__device__ int   g_rowptr[N_DST + 1];
__device__ int   g_cursor[N_DST];
__device__ int   g_packed[E_TOT];            // src | (neg_flag << 31)
__device__ unsigned char g_flags[E_TOT];     // zeroed by scatter after reading
__device__ float g_hneg[N_DST * HDIM];
__device__ float g_loss;                     // zeroed by finalize after reading
// B fragments in mma lane order: [kstep 0..15][ntile 0..15][lane 0..31] = (b0hi,b1hi,b0lo,b1lo)
__device__ float4 g_bfrag[16 * 16 * 32];

__device__ __forceinline__ float tf32_hi(float x) {
    return __uint_as_float(__float_as_uint(x) & 0xFFFFE000u);
}

__device__ __forceinline__ void mma_tf32(float* d, unsigned a0, unsigned a1,
                                         unsigned a2, unsigned a3,
                                         unsigned b0, unsigned b1) {
    asm volatile(
        "mma.sync.aligned.m16n8k8.row.col.f32.tf32.tf32.f32 "
        "{%0,%1,%2,%3}, {%4,%5,%6,%7}, {%8,%9}, {%0,%1,%2,%3};\n"
        : "+f"(d[0]), "+f"(d[1]), "+f"(d[2]), "+f"(d[3])
        : "r"(a0), "r"(a1), "r"(a2), "r"(a3), "r"(b0), "r"(b1));
}

// ---------------------------------------------------------------------------
// 0) Pre-swizzle fc_w (128x128) into mma.m16n8k8 B-fragment order with hi/lo
//    tf32 split.
// ---------------------------------------------------------------------------
__global__ void bprep_kernel(const float* __restrict__ fc_w) {
    int i = blockIdx.x * blockDim.x + threadIdx.x;
    if (i >= 16 * 16 * 32) return;
    int lane = i & 31;
    int nt = (i >> 5) & 15;
    int ks = i >> 9;
    int k = ks * 8 + (lane & 3);       // threadID_in_group -> k row
    int n = nt * 8 + (lane >> 2);      // groupID -> n col
    float b0 = fc_w[k * FDIM + n];
    float b1 = fc_w[(k + 4) * FDIM + n];
    float b0h = tf32_hi(b0), b1h = tf32_hi(b1);
    g_bfrag[i] = make_float4(b0h, b1h, b0 - b0h, b1 - b1h);
}

// ---------------------------------------------------------------------------
// 1) flags + hist fused (independent target arrays, no ordering needed)
// ---------------------------------------------------------------------------
__global__ void flagshist_kernel(const int* __restrict__ neg_idx, int e_neg,
                                 const int* __restrict__ edge_dst) {
    int i = blockIdx.x * blockDim.x + threadIdx.x;
    if (i < E_TOT / 4) {
        int4 d = ((const int4*)edge_dst)[i];
        atomicAdd(&g_counts[d.x - N_SRC], 1);
        atomicAdd(&g_counts[d.y - N_SRC], 1);
        atomicAdd(&g_counts[d.z - N_SRC], 1);
        atomicAdd(&g_counts[d.w - N_SRC], 1);
    }
    if (i < e_neg) g_flags[neg_idx[i]] = 1;
}

// ---------------------------------------------------------------------------
// 2) Exclusive scan: single block, 1024 threads, 20 elems/thread, 2 barriers.
//    Restores g_counts to zero for the next replay.
// ---------------------------------------------------------------------------
__global__ void scan_kernel() {
    const int PER = 20;  // 1024*20 = 20480 >= N_DST
    __shared__ int ws[32];
    const int t = threadIdx.x;
    const int lane = t & 31, wid = t >> 5;
    const int base = t * PER;

    int loc[PER];
    int s = 0;
    #pragma unroll
    for (int j = 0; j < PER; j++) {
        int idx = base + j;
        int v = (idx < N_DST) ? g_counts[idx] : 0;
        loc[j] = s;
        s += v;
    }
    int inc = s;
    #pragma unroll
    for (int off = 1; off < 32; off <<= 1) {
        int v = __shfl_up_sync(0xffffffffu, inc, off);
        if (lane >= off) inc += v;
    }
    if (lane == 31) ws[wid] = inc;
    __syncthreads();
    if (wid == 0) {
        int v = ws[lane];
        int winc = v;
        #pragma unroll
        for (int off = 1; off < 32; off <<= 1) {
            int u = __shfl_up_sync(0xffffffffu, winc, off);
            if (lane >= off) winc += u;
        }
        ws[lane] = winc - v;  // exclusive warp offset
    }
    __syncthreads();
    int off = ws[wid] + inc - s;  // exclusive thread offset
    #pragma unroll
    for (int j = 0; j < PER; j++) {
        int idx = base + j;
        if (idx < N_DST) {
            int e = off + loc[j];
            g_rowptr[idx] = e;
            g_cursor[idx] = e;
            g_counts[idx] = 0;   // restore invariant for next replay
        }
    }
    if (t == 1023) g_rowptr[N_DST] = off + s;
}

// ---------------------------------------------------------------------------
// 3) z = feat @ fc_w via tf32 tensor cores, 3xTF32 split; el/er fused into
//    the epilogue. Block = 64 rows staged in padded smem (conflict-free
//    fragment LDS replaces the 8-wavefront scalar A LDGs). Warp = 32 rows x
//    32 cols: two m16 row-tiles share every B fragment.
// ---------------------------------------------------------------------------
__global__ void __launch_bounds__(256) gemm_kernel(const float* __restrict__ feat,
                                                   const float* __restrict__ attn_l,
                                                   const float* __restrict__ attn_r) {
    __shared__ float sA[64][132];            // pad 4 -> bank = (4*row + col) & 31
    const int tid = threadIdx.x;
    const int rowB = blockIdx.x * 64;

    // stage A: 64 rows x 128 cols, coalesced float4 (each row loaded ONCE)
    for (int it = tid; it < 64 * 32; it += 256) {
        int r = it >> 5, c4 = it & 31;
        float4 v = *(const float4*)(feat + (size_t)(rowB + r) * FDIM + c4 * 4);
        *(float4*)(&sA[r][c4 * 4]) = v;
    }
    __syncthreads();

    const int w = tid >> 5;              // warp in block: 0..7
    const int rt_base = (w >> 2) * 32;   // 0 or 32 (local row base of warp tile)
    const int ct = w & 3;                // column quarter: cols [32*ct, 32*ct+32)
    const int lane = tid & 31;
    const int g = lane >> 2;             // groupID (row within m16 tile)
    const int tg = lane & 3;             // threadID_in_group

    float acc[2][4][4];
    #pragma unroll
    for (int rt = 0; rt < 2; rt++)
        #pragma unroll
        for (int nt = 0; nt < 4; nt++) {
            acc[rt][nt][0] = 0.f; acc[rt][nt][1] = 0.f;
            acc[rt][nt][2] = 0.f; acc[rt][nt][3] = 0.f;
        }

    #pragma unroll 1
    for (int ks = 0; ks < 16; ks++) {
        const int c = ks * 8 + tg;
        // A fragments from smem (all conflict-free: banks 4g+tg distinct)
        float aA0 = sA[rt_base + g][c];
        float aA1 = sA[rt_base + g + 8][c];
        float aA2 = sA[rt_base + g][c + 4];
        float aA3 = sA[rt_base + g + 8][c + 4];
        float aB0 = sA[rt_base + g + 16][c];
        float aB1 = sA[rt_base + g + 24][c];
        float aB2 = sA[rt_base + g + 16][c + 4];
        float aB3 = sA[rt_base + g + 24][c + 4];
        unsigned hA0 = __float_as_uint(aA0) & 0xFFFFE000u;
        unsigned hA1 = __float_as_uint(aA1) & 0xFFFFE000u;
        unsigned hA2 = __float_as_uint(aA2) & 0xFFFFE000u;
        unsigned hA3 = __float_as_uint(aA3) & 0xFFFFE000u;
        unsigned lA0 = __float_as_uint(aA0 - __uint_as_float(hA0));
        unsigned lA1 = __float_as_uint(aA1 - __uint_as_float(hA1));
        unsigned lA2 = __float_as_uint(aA2 - __uint_as_float(hA2));
        unsigned lA3 = __float_as_uint(aA3 - __uint_as_float(hA3));
        unsigned hB0 = __float_as_uint(aB0) & 0xFFFFE000u;
        unsigned hB1 = __float_as_uint(aB1) & 0xFFFFE000u;
        unsigned hB2 = __float_as_uint(aB2) & 0xFFFFE000u;
        unsigned hB3 = __float_as_uint(aB3) & 0xFFFFE000u;
        unsigned lB0 = __float_as_uint(aB0 - __uint_as_float(hB0));
        unsigned lB1 = __float_as_uint(aB1 - __uint_as_float(hB1));
        unsigned lB2 = __float_as_uint(aB2 - __uint_as_float(hB2));
        unsigned lB3 = __float_as_uint(aB3 - __uint_as_float(hB3));

        const float4* bp = g_bfrag + ks * 16 * 32 + (ct * 4) * 32 + lane;
        #pragma unroll
        for (int nt = 0; nt < 4; nt++) {
            float4 b = bp[nt * 32];
            unsigned bx = __float_as_uint(b.x), by = __float_as_uint(b.y);
            unsigned bz = __float_as_uint(b.z), bw = __float_as_uint(b.w);
            // row-tile 0
            mma_tf32(acc[0][nt], hA0, hA1, hA2, hA3, bx, by);   // hi * hi
            mma_tf32(acc[0][nt], lA0, lA1, lA2, lA3, bx, by);   // lo * hi
            mma_tf32(acc[0][nt], hA0, hA1, hA2, hA3, bz, bw);   // hi * lo
            // row-tile 1 (same B fragment)
            mma_tf32(acc[1][nt], hB0, hB1, hB2, hB3, bx, by);
            mma_tf32(acc[1][nt], lB0, lB1, lB2, lB3, bx, by);
            mma_tf32(acc[1][nt], hB0, hB1, hB2, hB3, bz, bw);
        }
    }

    // store z + fused el/er epilogue per row tile
    #pragma unroll
    for (int rt = 0; rt < 2; rt++) {
        const int rowbase = rowB + rt_base + rt * 16;
        float* zr0 = g_z + (size_t)(rowbase + g) * FDIM + ct * 32;
        float* zr1 = zr0 + 8 * FDIM;
        #pragma unroll
        for (int nt = 0; nt < 4; nt++) {
            *(float2*)(zr0 + nt * 8 + tg * 2) = make_float2(acc[rt][nt][0], acc[rt][nt][1]);
            *(float2*)(zr1 + nt * 8 + tg * 2) = make_float2(acc[rt][nt][2], acc[rt][nt][3]);
        }

        const int rA = (rowbase + g) * NHEAD;
        const int rB = (rowbase + g + 8) * NHEAD;
        #pragma unroll
        for (int hh = 0; hh < 2; hh++) {
            const int h = ct * 2 + hh;
            const int nt0 = 2 * hh, nt1 = 2 * hh + 1;
            const float* alp = attn_l + h * HDIM + tg * 2;
            const float* arp = attn_r + h * HDIM + tg * 2;
            float2 al0 = *(const float2*)(alp);
            float2 al1 = *(const float2*)(alp + 8);
            float2 arr0 = *(const float2*)(arp);
            float2 arr1 = *(const float2*)(arp + 8);
            float elA = acc[rt][nt0][0] * al0.x + acc[rt][nt0][1] * al0.y
                      + acc[rt][nt1][0] * al1.x + acc[rt][nt1][1] * al1.y;
            float elB = acc[rt][nt0][2] * al0.x + acc[rt][nt0][3] * al0.y
                      + acc[rt][nt1][2] * al1.x + acc[rt][nt1][3] * al1.y;
            float erA = acc[rt][nt0][0] * arr0.x + acc[rt][nt0][1] * arr0.y
                      + acc[rt][nt1][0] * arr1.x + acc[rt][nt1][1] * arr1.y;
            float erB = acc[rt][nt0][2] * arr0.x + acc[rt][nt0][3] * arr0.y
                      + acc[rt][nt1][2] * arr1.x + acc[rt][nt1][3] * arr1.y;
            elA += __shfl_xor_sync(0xffffffffu, elA, 1);
            elA += __shfl_xor_sync(0xffffffffu, elA, 2);
            elB += __shfl_xor_sync(0xffffffffu, elB, 1);
            elB += __shfl_xor_sync(0xffffffffu, elB, 2);
            erA += __shfl_xor_sync(0xffffffffu, erA, 1);
            erA += __shfl_xor_sync(0xffffffffu, erA, 2);
            erB += __shfl_xor_sync(0xffffffffu, erB, 1);
            erB += __shfl_xor_sync(0xffffffffu, erB, 2);
            if (tg == 0) {
                g_el[rA + h] = elA;
                g_el[rB + h] = elB;
                g_er[rA + h] = erA;
                g_er[rB + h] = erB;
            }
        }
    }
}

// ---------------------------------------------------------------------------
// 4) Scatter edges into CSR; restores g_flags to zero after reading.
// ---------------------------------------------------------------------------
__global__ void scatter_kernel(const int* __restrict__ edge_src,
                               const int* __restrict__ edge_dst) {
    int i = blockIdx.x * blockDim.x + threadIdx.x;
    if (i >= E_TOT / 4) return;
    int4 sv = ((const int4*)edge_src)[i];
    int4 dv = ((const int4*)edge_dst)[i];
    int fl = ((const int*)g_flags)[i];
    ((int*)g_flags)[i] = 0;              // restore invariant for next replay
    int p0 = atomicAdd(&g_cursor[dv.x - N_SRC], 1);
    g_packed[p0] = sv.x | ((fl & 1) << 31);
    int p1 = atomicAdd(&g_cursor[dv.y - N_SRC], 1);
    g_packed[p1] = sv.y | (((fl >> 8) & 1) << 31);
    int p2 = atomicAdd(&g_cursor[dv.z - N_SRC], 1);
    g_packed[p2] = sv.z | (((fl >> 16) & 1) << 31);
    int p3 = atomicAdd(&g_cursor[dv.w - N_SRC], 1);
    g_packed[p3] = sv.w | (((fl >> 24) & 1) << 31);
}

// ---------------------------------------------------------------------------
// 5) Aggregation: one warp per dst node, fused pos+neg, shift-softmax,
//    4-deep software pipeline (proven best; 8-deep regressed via register
//    pressure), per-node loss fused (atomicAdd to g_loss).
// ---------------------------------------------------------------------------
#define AGG_LOAD(J, IDX)                                                     \
    {                                                                        \
        int _i = (IDX);                                                      \
        if (_i < pend) {                                                     \
            unsigned _u = (unsigned)g_packed[_i];                            \
            u##J = _u;                                                       \
            int _s = (int)(_u & 0x7fffffffu);                                \
            el##J = g_el[_s * NHEAD + h];                                    \
            z##J = *(const float4*)(g_z + (size_t)_s * FDIM + lane * 4);     \
        }                                                                    \
    }

#define AGG_PROC(J, IDX)                                                     \
    if ((IDX) < pend) {                                                      \
        float _e = el##J + er_h;                                             \
        _e = (_e >= 0.f) ? _e : NEG_SLOPE * _e;                              \
        float _w = __expf(_e - E_SHIFT);                                     \
        dP += _w;                                                            \
        aP.x += _w * z##J.x; aP.y += _w * z##J.y;                            \
        aP.z += _w * z##J.z; aP.w += _w * z##J.w;                            \
        if (u##J >> 31) {                                                    \
            dN += _w;                                                        \
            aN.x += _w * z##J.x; aN.y += _w * z##J.y;                        \
            aN.z += _w * z##J.z; aN.w += _w * z##J.w;                        \
        }                                                                    \
    }

__global__ void aggregate_kernel(const float* __restrict__ bias,
                                 const float* __restrict__ prelu_a,
                                 float* __restrict__ out_pos) {
    const int warp = (blockIdx.x * blockDim.x + threadIdx.x) >> 5;
    if (warp >= N_DST) return;
    const int lane = threadIdx.x & 31;
    const int i = warp;
    const int n = N_SRC + i;
    const int h = lane >> 2;

    const float er_h = g_er[n * NHEAD + h];
    float4 zself = *(const float4*)(g_z + (size_t)n * FDIM + lane * 4);
    float e_self = g_el[n * NHEAD + h] + er_h;
    e_self = (e_self >= 0.f) ? e_self : NEG_SLOPE * e_self;
    float ws = __expf(e_self - E_SHIFT);

    float dP = ws, dN = ws;
    float4 aP = make_float4(ws * zself.x, ws * zself.y, ws * zself.z, ws * zself.w);
    float4 aN = aP;

    const int pbeg = g_rowptr[i], pend = g_rowptr[i + 1];

    unsigned u0 = 0, u1 = 0, u2 = 0, u3 = 0;
    float el0 = 0.f, el1 = 0.f, el2 = 0.f, el3 = 0.f;
    float4 z0 = {}, z1 = {}, z2 = {}, z3 = {};

    AGG_LOAD(0, pbeg + 0);
    AGG_LOAD(1, pbeg + 1);
    AGG_LOAD(2, pbeg + 2);
    AGG_LOAD(3, pbeg + 3);

    #pragma unroll 1
    for (int k = pbeg; k < pend; k += 4) {
        AGG_PROC(0, k + 0); AGG_LOAD(0, k + 4);
        AGG_PROC(1, k + 1); AGG_LOAD(1, k + 5);
        AGG_PROC(2, k + 2); AGG_LOAD(2, k + 6);
        AGG_PROC(3, k + 3); AGG_LOAD(3, k + 7);
    }

    const float pa = prelu_a[0];
    const int f0 = lane * 4;
    float b0 = bias[f0], b1 = bias[f0 + 1], b2 = bias[f0 + 2], b3 = bias[f0 + 3];

    float pv0, pv1, pv2, pv3, nv0, nv1, nv2, nv3;
    {   // positive
        float inv = 1.f / dP;
        float v0 = aP.x * inv + b0; v0 = (v0 >= 0.f) ? v0 : pa * v0;
        float v1 = aP.y * inv + b1; v1 = (v1 >= 0.f) ? v1 : pa * v1;
        float v2 = aP.z * inv + b2; v2 = (v2 >= 0.f) ? v2 : pa * v2;
        float v3 = aP.w * inv + b3; v3 = (v3 >= 0.f) ? v3 : pa * v3;
        #pragma unroll
        for (int off = 4; off <= 16; off <<= 1) {
            v0 += __shfl_xor_sync(0xffffffffu, v0, off);
            v1 += __shfl_xor_sync(0xffffffffu, v1, off);
            v2 += __shfl_xor_sync(0xffffffffu, v2, off);
            v3 += __shfl_xor_sync(0xffffffffu, v3, off);
        }
        pv0 = v0 * 0.125f; pv1 = v1 * 0.125f; pv2 = v2 * 0.125f; pv3 = v3 * 0.125f;
        if (lane < 4) {
            float* o = out_pos + (size_t)i * HDIM + lane * 4;
            o[0] = pv0; o[1] = pv1; o[2] = pv2; o[3] = pv3;
        }
    }
    {   // negative
        float inv = 1.f / dN;
        float v0 = aN.x * inv + b0; v0 = (v0 >= 0.f) ? v0 : pa * v0;
        float v1 = aN.y * inv + b1; v1 = (v1 >= 0.f) ? v1 : pa * v1;
        float v2 = aN.z * inv + b2; v2 = (v2 >= 0.f) ? v2 : pa * v2;
        float v3 = aN.w * inv + b3; v3 = (v3 >= 0.f) ? v3 : pa * v3;
        #pragma unroll
        for (int off = 4; off <= 16; off <<= 1) {
            v0 += __shfl_xor_sync(0xffffffffu, v0, off);
            v1 += __shfl_xor_sync(0xffffffffu, v1, off);
            v2 += __shfl_xor_sync(0xffffffffu, v2, off);
            v3 += __shfl_xor_sync(0xffffffffu, v3, off);
        }
        nv0 = v0 * 0.125f; nv1 = v1 * 0.125f; nv2 = v2 * 0.125f; nv3 = v3 * 0.125f;
    }

    // fused loss contribution
    float dot = pv0 * nv0 + pv1 * nv1 + pv2 * nv2 + pv3 * nv3;
    float na  = pv0 * pv0 + pv1 * pv1 + pv2 * pv2 + pv3 * pv3;
    float nb  = nv0 * nv0 + nv1 * nv1 + nv2 * nv2 + nv3 * nv3;
    dot += __shfl_xor_sync(0xffffffffu, dot, 1);
    dot += __shfl_xor_sync(0xffffffffu, dot, 2);
    na  += __shfl_xor_sync(0xffffffffu, na, 1);
    na  += __shfl_xor_sync(0xffffffffu, na, 2);
    nb  += __shfl_xor_sync(0xffffffffu, nb, 1);
    nb  += __shfl_xor_sync(0xffffffffu, nb, 2);
    if (lane == 0) {
        float den = fmaxf(sqrtf(na), 1e-8f) * fmaxf(sqrtf(nb), 1e-8f);
        atomicAdd(&g_loss, __expf(dot / den / TEM));
    }
}

// ---------------------------------------------------------------------------
// 6) finalize: out[0] = log(sum); reset accumulator for the next replay.
// ---------------------------------------------------------------------------
__global__ void finalize_kernel(float* __restrict__ out) {
    out[0] = logf(g_loss);
    g_loss = 0.f;
}

// ---------------------------------------------------------------------------
extern "C" void kernel_launch(void* const* d_in, const int* in_sizes, int n_in,
                              void* d_out, int out_size) {
    const float* feat    = (const float*)d_in[0];
    const float* fc_w    = (const float*)d_in[1];
    const float* attn_l  = (const float*)d_in[2];
    const float* attn_r  = (const float*)d_in[3];
    const float* bias    = (const float*)d_in[4];
    const float* prelu_a = (const float*)d_in[5];
    const int*   edge_src = (const int*)d_in[6];
    const int*   edge_dst = (const int*)d_in[7];
    const int*   neg_idx  = (const int*)d_in[8];
    const int    e_neg = in_sizes[8];

    float* out = (float*)d_out;          // [0] = loss, [1..] = h_pos (N_DST x 16)
    float* out_pos = out + 1;

    int fh_n = (e_neg > E_TOT / 4) ? e_neg : (E_TOT / 4);

    bprep_kernel<<<32, 256>>>(fc_w);                                          // 0
    flagshist_kernel<<<(fh_n + 255) / 256, 256>>>(neg_idx, e_neg, edge_dst);  // 1
    scan_kernel<<<1, 1024>>>();                                               // 2
    gemm_kernel<<<N_NODES / 64, 256>>>(feat, attn_l, attn_r);                 // 3 (profiled)
    scatter_kernel<<<(E_TOT / 4 + 255) / 256, 256>>>(edge_src, edge_dst);     // 4
    aggregate_kernel<<<(N_DST + 7) / 8, 256>>>(bias, prelu_a, out_pos);       // 5
    finalize_kernel<<<1, 1>>>(out);                                           // 6
}

// round 12
// speedup vs baseline: 1.3663x; 1.3663x over previous
#include <cuda_runtime.h>
#include <cstdint>

// Problem constants (match reference)
#define N_SRC   20000
#define N_DST   20000
#define N_NODES 40000
#define E_TOT   320000
#define NHEAD   8
#define HDIM    16
#define FDIM    128
#define TEM     0.7f
#define NEG_SLOPE 0.2f
#define E_SHIFT 10.0f   // constant softmax shift; cancels in alpha = w / sum(w)

// Scratch (device globals; zero-initialized at module load; every launch
// restores them to zero where required -> deterministic across graph replays)
__device__ float g_z[N_NODES * FDIM];        // 20.5 MB, L2-resident
__device__ float g_el[N_NODES * NHEAD];
__device__ float g_er[N_NODES * NHEAD];
__device__ int   g_counts[N_DST];            // zeroed by scan after reading
__device__ int   g_rowptr[N_DST + 1];
__device__ int   g_cursor[N_DST];
__device__ int   g_packed[E_TOT];            // src | (neg_flag << 31)
__device__ unsigned char g_flags[E_TOT];     // zeroed by scatter after reading
__device__ float g_hneg[N_DST * HDIM];
__device__ float g_loss;                     // zeroed by finalize after reading
// B fragments in mma lane order: [kstep 0..15][ntile 0..15][lane 0..31] = (b0hi,b1hi,b0lo,b1lo)
__device__ float4 g_bfrag[16 * 16 * 32];

__device__ __forceinline__ float tf32_hi(float x) {
    return __uint_as_float(__float_as_uint(x) & 0xFFFFE000u);
}

__device__ __forceinline__ void mma_tf32(float* d, unsigned a0, unsigned a1,
                                         unsigned a2, unsigned a3,
                                         unsigned b0, unsigned b1) {
    asm volatile(
        "mma.sync.aligned.m16n8k8.row.col.f32.tf32.tf32.f32 "
        "{%0,%1,%2,%3}, {%4,%5,%6,%7}, {%8,%9}, {%0,%1,%2,%3};\n"
        : "+f"(d[0]), "+f"(d[1]), "+f"(d[2]), "+f"(d[3])
        : "r"(a0), "r"(a1), "r"(a2), "r"(a3), "r"(b0), "r"(b1));
}

// ---------------------------------------------------------------------------
// 0) Pre-swizzle fc_w (128x128) into mma.m16n8k8 B-fragment order with hi/lo
//    tf32 split.
// ---------------------------------------------------------------------------
__global__ void bprep_kernel(const float* __restrict__ fc_w) {
    int i = blockIdx.x * blockDim.x + threadIdx.x;
    if (i >= 16 * 16 * 32) return;
    int lane = i & 31;
    int nt = (i >> 5) & 15;
    int ks = i >> 9;
    int k = ks * 8 + (lane & 3);       // threadID_in_group -> k row
    int n = nt * 8 + (lane >> 2);      // groupID -> n col
    float b0 = fc_w[k * FDIM + n];
    float b1 = fc_w[(k + 4) * FDIM + n];
    float b0h = tf32_hi(b0), b1h = tf32_hi(b1);
    g_bfrag[i] = make_float4(b0h, b1h, b0 - b0h, b1 - b1h);
}

// ---------------------------------------------------------------------------
// 1) flags + hist fused (independent target arrays, no ordering needed)
// ---------------------------------------------------------------------------
__global__ void flagshist_kernel(const int* __restrict__ neg_idx, int e_neg,
                                 const int* __restrict__ edge_dst) {
    int i = blockIdx.x * blockDim.x + threadIdx.x;
    if (i < E_TOT / 4) {
        int4 d = ((const int4*)edge_dst)[i];
        atomicAdd(&g_counts[d.x - N_SRC], 1);
        atomicAdd(&g_counts[d.y - N_SRC], 1);
        atomicAdd(&g_counts[d.z - N_SRC], 1);
        atomicAdd(&g_counts[d.w - N_SRC], 1);
    }
    if (i < e_neg) g_flags[neg_idx[i]] = 1;
}

// ---------------------------------------------------------------------------
// 2) Exclusive scan: single block, 1024 threads, 20 elems/thread, 2 barriers.
//    Restores g_counts to zero for the next replay.
// ---------------------------------------------------------------------------
__global__ void scan_kernel() {
    const int PER = 20;  // 1024*20 = 20480 >= N_DST
    __shared__ int ws[32];
    const int t = threadIdx.x;
    const int lane = t & 31, wid = t >> 5;
    const int base = t * PER;

    int loc[PER];
    int s = 0;
    #pragma unroll
    for (int j = 0; j < PER; j++) {
        int idx = base + j;
        int v = (idx < N_DST) ? g_counts[idx] : 0;
        loc[j] = s;
        s += v;
    }
    int inc = s;
    #pragma unroll
    for (int off = 1; off < 32; off <<= 1) {
        int v = __shfl_up_sync(0xffffffffu, inc, off);
        if (lane >= off) inc += v;
    }
    if (lane == 31) ws[wid] = inc;
    __syncthreads();
    if (wid == 0) {
        int v = ws[lane];
        int winc = v;
        #pragma unroll
        for (int off = 1; off < 32; off <<= 1) {
            int u = __shfl_up_sync(0xffffffffu, winc, off);
            if (lane >= off) winc += u;
        }
        ws[lane] = winc - v;  // exclusive warp offset
    }
    __syncthreads();
    int off = ws[wid] + inc - s;  // exclusive thread offset
    #pragma unroll
    for (int j = 0; j < PER; j++) {
        int idx = base + j;
        if (idx < N_DST) {
            int e = off + loc[j];
            g_rowptr[idx] = e;
            g_cursor[idx] = e;
            g_counts[idx] = 0;   // restore invariant for next replay
        }
    }
    if (t == 1023) g_rowptr[N_DST] = off + s;
}

// ---------------------------------------------------------------------------
// 3) z = feat @ fc_w via tf32 tensor cores, 3xTF32 split; el/er fused into
//    the epilogue. One warp = 16 rows x 64 cols (R7 config — best measured).
// ---------------------------------------------------------------------------
__global__ void __launch_bounds__(256) gemm_kernel(const float* __restrict__ feat,
                                                   const float* __restrict__ attn_l,
                                                   const float* __restrict__ attn_r) {
    const int gw = (blockIdx.x * blockDim.x + threadIdx.x) >> 5;  // 0..4999
    const int row0 = (gw >> 1) * 16;
    const int ct = gw & 1;             // column half: cols [64*ct, 64*ct+64)
    if (row0 >= N_NODES) return;
    const int lane = threadIdx.x & 31;
    const int g = lane >> 2;       // groupID (row within tile)
    const int tg = lane & 3;       // threadID_in_group

    const float* ar0 = feat + (size_t)(row0 + g) * FDIM;
    const float* ar1 = ar0 + 8 * FDIM;

    float acc[8][4];
    #pragma unroll
    for (int nt = 0; nt < 8; nt++) {
        acc[nt][0] = 0.f; acc[nt][1] = 0.f; acc[nt][2] = 0.f; acc[nt][3] = 0.f;
    }

    #pragma unroll 1
    for (int ks = 0; ks < 16; ks++) {
        float a0 = ar0[ks * 8 + tg];
        float a1 = ar1[ks * 8 + tg];
        float a2 = ar0[ks * 8 + tg + 4];
        float a3 = ar1[ks * 8 + tg + 4];
        unsigned h0 = __float_as_uint(a0) & 0xFFFFE000u;
        unsigned h1 = __float_as_uint(a1) & 0xFFFFE000u;
        unsigned h2 = __float_as_uint(a2) & 0xFFFFE000u;
        unsigned h3 = __float_as_uint(a3) & 0xFFFFE000u;
        unsigned l0 = __float_as_uint(a0 - __uint_as_float(h0));
        unsigned l1 = __float_as_uint(a1 - __uint_as_float(h1));
        unsigned l2 = __float_as_uint(a2 - __uint_as_float(h2));
        unsigned l3 = __float_as_uint(a3 - __uint_as_float(h3));

        const float4* bp = g_bfrag + ks * 16 * 32 + (ct * 8) * 32 + lane;
        #pragma unroll
        for (int nt = 0; nt < 8; nt++) {
            float4 b = bp[nt * 32];
            unsigned bx = __float_as_uint(b.x), by = __float_as_uint(b.y);
            unsigned bz = __float_as_uint(b.z), bw = __float_as_uint(b.w);
            mma_tf32(acc[nt], h0, h1, h2, h3, bx, by);   // hi * hi
            mma_tf32(acc[nt], l0, l1, l2, l3, bx, by);   // lo * hi
            mma_tf32(acc[nt], h0, h1, h2, h3, bz, bw);   // hi * lo
        }
    }

    // store z (this warp's column half)
    float* zr0 = g_z + (size_t)(row0 + g) * FDIM + ct * 64;
    float* zr1 = zr0 + 8 * FDIM;
    #pragma unroll
    for (int nt = 0; nt < 8; nt++) {
        *(float2*)(zr0 + nt * 8 + tg * 2) = make_float2(acc[nt][0], acc[nt][1]);
        *(float2*)(zr1 + nt * 8 + tg * 2) = make_float2(acc[nt][2], acc[nt][3]);
    }

    // fused el/er epilogue: this half holds heads h = ct*4 + hh, hh=0..3
    const int rA = (row0 + g) * NHEAD;
    const int rB = (row0 + g + 8) * NHEAD;
    #pragma unroll
    for (int hh = 0; hh < 4; hh++) {
        const int h = ct * 4 + hh;
        const int nt0 = 2 * hh, nt1 = 2 * hh + 1;
        const float* alp = attn_l + h * HDIM + tg * 2;
        const float* arp = attn_r + h * HDIM + tg * 2;
        float2 al0 = *(const float2*)(alp);
        float2 al1 = *(const float2*)(alp + 8);
        float2 arr0 = *(const float2*)(arp);
        float2 arr1 = *(const float2*)(arp + 8);
        float elA = acc[nt0][0] * al0.x + acc[nt0][1] * al0.y
                  + acc[nt1][0] * al1.x + acc[nt1][1] * al1.y;
        float elB = acc[nt0][2] * al0.x + acc[nt0][3] * al0.y
                  + acc[nt1][2] * al1.x + acc[nt1][3] * al1.y;
        float erA = acc[nt0][0] * arr0.x + acc[nt0][1] * arr0.y
                  + acc[nt1][0] * arr1.x + acc[nt1][1] * arr1.y;
        float erB = acc[nt0][2] * arr0.x + acc[nt0][3] * arr0.y
                  + acc[nt1][2] * arr1.x + acc[nt1][3] * arr1.y;
        elA += __shfl_xor_sync(0xffffffffu, elA, 1);
        elA += __shfl_xor_sync(0xffffffffu, elA, 2);
        elB += __shfl_xor_sync(0xffffffffu, elB, 1);
        elB += __shfl_xor_sync(0xffffffffu, elB, 2);
        erA += __shfl_xor_sync(0xffffffffu, erA, 1);
        erA += __shfl_xor_sync(0xffffffffu, erA, 2);
        erB += __shfl_xor_sync(0xffffffffu, erB, 1);
        erB += __shfl_xor_sync(0xffffffffu, erB, 2);
        if (tg == 0) {
            g_el[rA + h] = elA;
            g_el[rB + h] = elB;
            g_er[rA + h] = erA;
            g_er[rB + h] = erB;
        }
    }
}

// ---------------------------------------------------------------------------
// 4) Scatter edges into CSR; restores g_flags to zero after reading.
// ---------------------------------------------------------------------------
__global__ void scatter_kernel(const int* __restrict__ edge_src,
                               const int* __restrict__ edge_dst) {
    int i = blockIdx.x * blockDim.x + threadIdx.x;
    if (i >= E_TOT / 4) return;
    int4 sv = ((const int4*)edge_src)[i];
    int4 dv = ((const int4*)edge_dst)[i];
    int fl = ((const int*)g_flags)[i];
    ((int*)g_flags)[i] = 0;              // restore invariant for next replay
    int p0 = atomicAdd(&g_cursor[dv.x - N_SRC], 1);
    g_packed[p0] = sv.x | ((fl & 1) << 31);
    int p1 = atomicAdd(&g_cursor[dv.y - N_SRC], 1);
    g_packed[p1] = sv.y | (((fl >> 8) & 1) << 31);
    int p2 = atomicAdd(&g_cursor[dv.z - N_SRC], 1);
    g_packed[p2] = sv.z | (((fl >> 16) & 1) << 31);
    int p3 = atomicAdd(&g_cursor[dv.w - N_SRC], 1);
    g_packed[p3] = sv.w | (((fl >> 24) & 1) << 31);
}

// ---------------------------------------------------------------------------
// 5) Aggregation: one warp per dst node, fused pos+neg, shift-softmax.
//    8-deep cp.async pipeline: z gathers staged into smem (no result regs
//    held while in flight); u/el stay in an 8-deep register pipeline.
//    Each lane cp.asyncs and reads back only its OWN 16B chunk -> no syncwarp.
//    commit_group is UNCONDITIONAL so group counts align with wait_group 7.
// ---------------------------------------------------------------------------
#define AGG_ISSUE(J, IDX)                                                    \
    {                                                                        \
        int _i = (IDX);                                                      \
        if (_i < pend) {                                                     \
            unsigned _u = (unsigned)g_packed[_i];                            \
            u##J = _u;                                                       \
            int _s = (int)(_u & 0x7fffffffu);                                \
            el##J = g_el[_s * NHEAD + h];                                    \
            asm volatile("cp.async.cg.shared.global [%0], [%1], 16;\n"       \
                         :: "r"(sb + (J) * 512),                             \
                            "l"(g_z + (size_t)_s * FDIM + lane * 4)          \
                         : "memory");                                        \
        }                                                                    \
        asm volatile("cp.async.commit_group;\n" ::: "memory");               \
    }

#define AGG_PROC(J, IDX)                                                     \
    asm volatile("cp.async.wait_group 7;\n" ::: "memory");                   \
    if ((IDX) < pend) {                                                      \
        float4 zs = sbuf[wslot][J][lane];                                    \
        float _e = el##J + er_h;                                             \
        _e = (_e >= 0.f) ? _e : NEG_SLOPE * _e;                              \
        float _w = __expf(_e - E_SHIFT);                                     \
        dP += _w;                                                            \
        aP.x += _w * zs.x; aP.y += _w * zs.y;                                \
        aP.z += _w * zs.z; aP.w += _w * zs.w;                                \
        if (u##J >> 31) {                                                    \
            dN += _w;                                                        \
            aN.x += _w * zs.x; aN.y += _w * zs.y;                            \
            aN.z += _w * zs.z; aN.w += _w * zs.w;                            \
        }                                                                    \
    }

__global__ void __launch_bounds__(256) aggregate_kernel(const float* __restrict__ bias,
                                                        const float* __restrict__ prelu_a,
                                                        float* __restrict__ out_pos) {
    __shared__ float4 sbuf[8][8][32];    // [warp][stage][lane] = 32 KB
    const int warp = (blockIdx.x * blockDim.x + threadIdx.x) >> 5;
    if (warp >= N_DST) return;           // never taken: grid covers exactly N_DST warps
    const int wslot = threadIdx.x >> 5;
    const int lane = threadIdx.x & 31;
    const int i = warp;
    const int n = N_SRC + i;
    const int h = lane >> 2;

    // 32-bit smem address of this lane's slot in stage 0 of this warp's buffer
    const unsigned sb =
        (unsigned)__cvta_generic_to_shared(&sbuf[wslot][0][lane]);

    const float er_h = g_er[n * NHEAD + h];
    float4 zself = *(const float4*)(g_z + (size_t)n * FDIM + lane * 4);
    float e_self = g_el[n * NHEAD + h] + er_h;
    e_self = (e_self >= 0.f) ? e_self : NEG_SLOPE * e_self;
    float ws = __expf(e_self - E_SHIFT);

    float dP = ws, dN = ws;
    float4 aP = make_float4(ws * zself.x, ws * zself.y, ws * zself.z, ws * zself.w);
    float4 aN = aP;

    const int pbeg = g_rowptr[i], pend = g_rowptr[i + 1];

    unsigned u0 = 0, u1 = 0, u2 = 0, u3 = 0, u4 = 0, u5 = 0, u6 = 0, u7 = 0;
    float el0 = 0.f, el1 = 0.f, el2 = 0.f, el3 = 0.f;
    float el4 = 0.f, el5 = 0.f, el6 = 0.f, el7 = 0.f;

    AGG_ISSUE(0, pbeg + 0);
    AGG_ISSUE(1, pbeg + 1);
    AGG_ISSUE(2, pbeg + 2);
    AGG_ISSUE(3, pbeg + 3);
    AGG_ISSUE(4, pbeg + 4);
    AGG_ISSUE(5, pbeg + 5);
    AGG_ISSUE(6, pbeg + 6);
    AGG_ISSUE(7, pbeg + 7);

    #pragma unroll 1
    for (int k = pbeg; k < pend; k += 8) {
        AGG_PROC(0, k + 0); AGG_ISSUE(0, k + 8);
        AGG_PROC(1, k + 1); AGG_ISSUE(1, k + 9);
        AGG_PROC(2, k + 2); AGG_ISSUE(2, k + 10);
        AGG_PROC(3, k + 3); AGG_ISSUE(3, k + 11);
        AGG_PROC(4, k + 4); AGG_ISSUE(4, k + 12);
        AGG_PROC(5, k + 5); AGG_ISSUE(5, k + 13);
        AGG_PROC(6, k + 6); AGG_ISSUE(6, k + 14);
        AGG_PROC(7, k + 7); AGG_ISSUE(7, k + 15);
    }
    // drain remaining async groups (writes only our own smem; must complete
    // before smem reuse by a later block on this SM is handled by HW retire)
    asm volatile("cp.async.wait_group 0;\n" ::: "memory");

    const float pa = prelu_a[0];
    const int f0 = lane * 4;
    float b0 = bias[f0], b1 = bias[f0 + 1], b2 = bias[f0 + 2], b3 = bias[f0 + 3];

    float pv0, pv1, pv2, pv3, nv0, nv1, nv2, nv3;
    {   // positive
        float inv = 1.f / dP;
        float v0 = aP.x * inv + b0; v0 = (v0 >= 0.f) ? v0 : pa * v0;
        float v1 = aP.y * inv + b1; v1 = (v1 >= 0.f) ? v1 : pa * v1;
        float v2 = aP.z * inv + b2; v2 = (v2 >= 0.f) ? v2 : pa * v2;
        float v3 = aP.w * inv + b3; v3 = (v3 >= 0.f) ? v3 : pa * v3;
        #pragma unroll
        for (int off = 4; off <= 16; off <<= 1) {
            v0 += __shfl_xor_sync(0xffffffffu, v0, off);
            v1 += __shfl_xor_sync(0xffffffffu, v1, off);
            v2 += __shfl_xor_sync(0xffffffffu, v2, off);
            v3 += __shfl_xor_sync(0xffffffffu, v3, off);
        }
        pv0 = v0 * 0.125f; pv1 = v1 * 0.125f; pv2 = v2 * 0.125f; pv3 = v3 * 0.125f;
        if (lane < 4) {
            float* o = out_pos + (size_t)i * HDIM + lane * 4;
            o[0] = pv0; o[1] = pv1; o[2] = pv2; o[3] = pv3;
        }
    }
    {   // negative
        float inv = 1.f / dN;
        float v0 = aN.x * inv + b0; v0 = (v0 >= 0.f) ? v0 : pa * v0;
        float v1 = aN.y * inv + b1; v1 = (v1 >= 0.f) ? v1 : pa * v1;
        float v2 = aN.z * inv + b2; v2 = (v2 >= 0.f) ? v2 : pa * v2;
        float v3 = aN.w * inv + b3; v3 = (v3 >= 0.f) ? v3 : pa * v3;
        #pragma unroll
        for (int off = 4; off <= 16; off <<= 1) {
            v0 += __shfl_xor_sync(0xffffffffu, v0, off);
            v1 += __shfl_xor_sync(0xffffffffu, v1, off);
            v2 += __shfl_xor_sync(0xffffffffu, v2, off);
            v3 += __shfl_xor_sync(0xffffffffu, v3, off);
        }
        nv0 = v0 * 0.125f; nv1 = v1 * 0.125f; nv2 = v2 * 0.125f; nv3 = v3 * 0.125f;
    }

    // fused loss contribution
    float dot = pv0 * nv0 + pv1 * nv1 + pv2 * nv2 + pv3 * nv3;
    float na  = pv0 * pv0 + pv1 * pv1 + pv2 * pv2 + pv3 * pv3;
    float nb  = nv0 * nv0 + nv1 * nv1 + nv2 * nv2 + nv3 * nv3;
    dot += __shfl_xor_sync(0xffffffffu, dot, 1);
    dot += __shfl_xor_sync(0xffffffffu, dot, 2);
    na  += __shfl_xor_sync(0xffffffffu, na, 1);
    na  += __shfl_xor_sync(0xffffffffu, na, 2);
    nb  += __shfl_xor_sync(0xffffffffu, nb, 1);
    nb  += __shfl_xor_sync(0xffffffffu, nb, 2);
    if (lane == 0) {
        float den = fmaxf(sqrtf(na), 1e-8f) * fmaxf(sqrtf(nb), 1e-8f);
        atomicAdd(&g_loss, __expf(dot / den / TEM));
    }
}

// ---------------------------------------------------------------------------
// 6) finalize: out[0] = log(sum); reset accumulator for the next replay.
// ---------------------------------------------------------------------------
__global__ void finalize_kernel(float* __restrict__ out) {
    out[0] = logf(g_loss);
    g_loss = 0.f;
}

// ---------------------------------------------------------------------------
extern "C" void kernel_launch(void* const* d_in, const int* in_sizes, int n_in,
                              void* d_out, int out_size) {
    const float* feat    = (const float*)d_in[0];
    const float* fc_w    = (const float*)d_in[1];
    const float* attn_l  = (const float*)d_in[2];
    const float* attn_r  = (const float*)d_in[3];
    const float* bias    = (const float*)d_in[4];
    const float* prelu_a = (const float*)d_in[5];
    const int*   edge_src = (const int*)d_in[6];
    const int*   edge_dst = (const int*)d_in[7];
    const int*   neg_idx  = (const int*)d_in[8];
    const int    e_neg = in_sizes[8];

    float* out = (float*)d_out;          // [0] = loss, [1..] = h_pos (N_DST x 16)
    float* out_pos = out + 1;

    int fh_n = (e_neg > E_TOT / 4) ? e_neg : (E_TOT / 4);

    bprep_kernel<<<32, 256>>>(fc_w);                                          // 0
    flagshist_kernel<<<(fh_n + 255) / 256, 256>>>(neg_idx, e_neg, edge_dst);  // 1
    scan_kernel<<<1, 1024>>>();                                               // 2
    gemm_kernel<<<(N_NODES / 16 * 2 * 32 + 255) / 256, 256>>>(feat, attn_l, attn_r); // 3 (profiled)
    scatter_kernel<<<(E_TOT / 4 + 255) / 256, 256>>>(edge_src, edge_dst);     // 4
    aggregate_kernel<<<(N_DST + 7) / 8, 256>>>(bias, prelu_a, out_pos);       // 5
    finalize_kernel<<<1, 1>>>(out);                                           // 6
}

// round 16
// speedup vs baseline: 1.3849x; 1.0137x over previous
#include <cuda_runtime.h>
#include <cstdint>

// Problem constants (match reference)
#define N_SRC   20000
#define N_DST   20000
#define N_NODES 40000
#define E_TOT   320000
#define NHEAD   8
#define HDIM    16
#define FDIM    128
#define TEM     0.7f
#define NEG_SLOPE 0.2f
#define E_SHIFT 10.0f   // constant softmax shift; cancels in alpha = w / sum(w)

#define GEMM_BLOCKS 625   // (N_NODES/16 * 2 warps) * 32 / 256

// Scratch (device globals; zero-initialized at module load; every launch
// restores them to zero where required -> deterministic across graph replays)
__device__ float g_z[N_NODES * FDIM];        // 20.5 MB, L2-resident
__device__ float g_el[N_NODES * NHEAD];
__device__ float g_er[N_NODES * NHEAD];
__device__ int   g_counts[N_DST];            // zeroed by scan after reading
__device__ int   g_rowptr[N_DST + 1];
__device__ int   g_cursor[N_DST];
__device__ int   g_packed[E_TOT];            // src | (neg_flag << 31)
__device__ unsigned char g_flags[E_TOT];     // zeroed by scatter after reading
__device__ float g_hneg[N_DST * HDIM];
__device__ float g_loss;                     // zeroed by finalize after reading
__device__ int   g_node_cursor;              // work-stealing cursor; reset by finalize
// B fragments in mma lane order: [kstep 0..15][ntile 0..15][lane 0..31] = (b0hi,b1hi,b0lo,b1lo)
__device__ float4 g_bfrag[16 * 16 * 32];

__device__ __forceinline__ float tf32_hi(float x) {
    return __uint_as_float(__float_as_uint(x) & 0xFFFFE000u);
}

__device__ __forceinline__ void mma_tf32(float* d, unsigned a0, unsigned a1,
                                         unsigned a2, unsigned a3,
                                         unsigned b0, unsigned b1) {
    asm volatile(
        "mma.sync.aligned.m16n8k8.row.col.f32.tf32.tf32.f32 "
        "{%0,%1,%2,%3}, {%4,%5,%6,%7}, {%8,%9}, {%0,%1,%2,%3};\n"
        : "+f"(d[0]), "+f"(d[1]), "+f"(d[2]), "+f"(d[3])
        : "r"(a0), "r"(a1), "r"(a2), "r"(a3), "r"(b0), "r"(b1));
}

// ---------------------------------------------------------------------------
// 0) Pre-swizzle fc_w (128x128) into mma.m16n8k8 B-fragment order with hi/lo
//    tf32 split.
// ---------------------------------------------------------------------------
__global__ void bprep_kernel(const float* __restrict__ fc_w) {
    int i = blockIdx.x * blockDim.x + threadIdx.x;
    if (i >= 16 * 16 * 32) return;
    int lane = i & 31;
    int nt = (i >> 5) & 15;
    int ks = i >> 9;
    int k = ks * 8 + (lane & 3);       // threadID_in_group -> k row
    int n = nt * 8 + (lane >> 2);      // groupID -> n col
    float b0 = fc_w[k * FDIM + n];
    float b1 = fc_w[(k + 4) * FDIM + n];
    float b0h = tf32_hi(b0), b1h = tf32_hi(b1);
    g_bfrag[i] = make_float4(b0h, b1h, b0 - b0h, b1 - b1h);
}

// ---------------------------------------------------------------------------
// 1) FUSED gemm + flags/hist: blocks [0, GEMM_BLOCKS) run the tf32 gemm with
//    fused el/er epilogue (R7 config, best measured); remaining blocks run
//    the edge histogram + neg-flag marking (independent data -> safe overlap).
// ---------------------------------------------------------------------------
__global__ void __launch_bounds__(256) gemmhist_kernel(const float* __restrict__ feat,
                                                       const float* __restrict__ attn_l,
                                                       const float* __restrict__ attn_r,
                                                       const int* __restrict__ neg_idx,
                                                       int e_neg,
                                                       const int* __restrict__ edge_dst) {
    if (blockIdx.x >= GEMM_BLOCKS) {
        // ---- flags + hist part ----
        int i = (blockIdx.x - GEMM_BLOCKS) * blockDim.x + threadIdx.x;
        if (i < E_TOT / 4) {
            int4 d = ((const int4*)edge_dst)[i];
            atomicAdd(&g_counts[d.x - N_SRC], 1);
            atomicAdd(&g_counts[d.y - N_SRC], 1);
            atomicAdd(&g_counts[d.z - N_SRC], 1);
            atomicAdd(&g_counts[d.w - N_SRC], 1);
        }
        if (i < e_neg) g_flags[neg_idx[i]] = 1;
        return;
    }

    // ---- gemm part: one warp = 16 rows x 64 cols ----
    const int gw = (blockIdx.x * blockDim.x + threadIdx.x) >> 5;  // 0..4999
    const int row0 = (gw >> 1) * 16;
    const int ct = gw & 1;             // column half: cols [64*ct, 64*ct+64)
    const int lane = threadIdx.x & 31;
    const int g = lane >> 2;       // groupID (row within tile)
    const int tg = lane & 3;       // threadID_in_group

    const float* ar0 = feat + (size_t)(row0 + g) * FDIM;
    const float* ar1 = ar0 + 8 * FDIM;

    float acc[8][4];
    #pragma unroll
    for (int nt = 0; nt < 8; nt++) {
        acc[nt][0] = 0.f; acc[nt][1] = 0.f; acc[nt][2] = 0.f; acc[nt][3] = 0.f;
    }

    #pragma unroll 1
    for (int ks = 0; ks < 16; ks++) {
        float a0 = ar0[ks * 8 + tg];
        float a1 = ar1[ks * 8 + tg];
        float a2 = ar0[ks * 8 + tg + 4];
        float a3 = ar1[ks * 8 + tg + 4];
        unsigned h0 = __float_as_uint(a0) & 0xFFFFE000u;
        unsigned h1 = __float_as_uint(a1) & 0xFFFFE000u;
        unsigned h2 = __float_as_uint(a2) & 0xFFFFE000u;
        unsigned h3 = __float_as_uint(a3) & 0xFFFFE000u;
        unsigned l0 = __float_as_uint(a0 - __uint_as_float(h0));
        unsigned l1 = __float_as_uint(a1 - __uint_as_float(h1));
        unsigned l2 = __float_as_uint(a2 - __uint_as_float(h2));
        unsigned l3 = __float_as_uint(a3 - __uint_as_float(h3));

        const float4* bp = g_bfrag + ks * 16 * 32 + (ct * 8) * 32 + lane;
        #pragma unroll
        for (int nt = 0; nt < 8; nt++) {
            float4 b = bp[nt * 32];
            unsigned bx = __float_as_uint(b.x), by = __float_as_uint(b.y);
            unsigned bz = __float_as_uint(b.z), bw = __float_as_uint(b.w);
            mma_tf32(acc[nt], h0, h1, h2, h3, bx, by);   // hi * hi
            mma_tf32(acc[nt], l0, l1, l2, l3, bx, by);   // lo * hi
            mma_tf32(acc[nt], h0, h1, h2, h3, bz, bw);   // hi * lo
        }
    }

    // store z (this warp's column half)
    float* zr0 = g_z + (size_t)(row0 + g) * FDIM + ct * 64;
    float* zr1 = zr0 + 8 * FDIM;
    #pragma unroll
    for (int nt = 0; nt < 8; nt++) {
        *(float2*)(zr0 + nt * 8 + tg * 2) = make_float2(acc[nt][0], acc[nt][1]);
        *(float2*)(zr1 + nt * 8 + tg * 2) = make_float2(acc[nt][2], acc[nt][3]);
    }

    // fused el/er epilogue: this half holds heads h = ct*4 + hh, hh=0..3
    const int rA = (row0 + g) * NHEAD;
    const int rB = (row0 + g + 8) * NHEAD;
    #pragma unroll
    for (int hh = 0; hh < 4; hh++) {
        const int h = ct * 4 + hh;
        const int nt0 = 2 * hh, nt1 = 2 * hh + 1;
        const float* alp = attn_l + h * HDIM + tg * 2;
        const float* arp = attn_r + h * HDIM + tg * 2;
        float2 al0 = *(const float2*)(alp);
        float2 al1 = *(const float2*)(alp + 8);
        float2 arr0 = *(const float2*)(arp);
        float2 arr1 = *(const float2*)(arp + 8);
        float elA = acc[nt0][0] * al0.x + acc[nt0][1] * al0.y
                  + acc[nt1][0] * al1.x + acc[nt1][1] * al1.y;
        float elB = acc[nt0][2] * al0.x + acc[nt0][3] * al0.y
                  + acc[nt1][2] * al1.x + acc[nt1][3] * al1.y;
        float erA = acc[nt0][0] * arr0.x + acc[nt0][1] * arr0.y
                  + acc[nt1][0] * arr1.x + acc[nt1][1] * arr1.y;
        float erB = acc[nt0][2] * arr0.x + acc[nt0][3] * arr0.y
                  + acc[nt1][2] * arr1.x + acc[nt1][3] * arr1.y;
        elA += __shfl_xor_sync(0xffffffffu, elA, 1);
        elA += __shfl_xor_sync(0xffffffffu, elA, 2);
        elB += __shfl_xor_sync(0xffffffffu, elB, 1);
        elB += __shfl_xor_sync(0xffffffffu, elB, 2);
        erA += __shfl_xor_sync(0xffffffffu, erA, 1);
        erA += __shfl_xor_sync(0xffffffffu, erA, 2);
        erB += __shfl_xor_sync(0xffffffffu, erB, 1);
        erB += __shfl_xor_sync(0xffffffffu, erB, 2);
        if (tg == 0) {
            g_el[rA + h] = elA;
            g_el[rB + h] = elB;
            g_er[rA + h] = erA;
            g_er[rB + h] = erB;
        }
    }
}

// ---------------------------------------------------------------------------
// 2) Exclusive scan: single block, 1024 threads, 20 elems/thread, 2 barriers.
//    Restores g_counts to zero for the next replay.
// ---------------------------------------------------------------------------
__global__ void scan_kernel() {
    const int PER = 20;  // 1024*20 = 20480 >= N_DST
    __shared__ int ws[32];
    const int t = threadIdx.x;
    const int lane = t & 31, wid = t >> 5;
    const int base = t * PER;

    int loc[PER];
    int s = 0;
    #pragma unroll
    for (int j = 0; j < PER; j++) {
        int idx = base + j;
        int v = (idx < N_DST) ? g_counts[idx] : 0;
        loc[j] = s;
        s += v;
    }
    int inc = s;
    #pragma unroll
    for (int off = 1; off < 32; off <<= 1) {
        int v = __shfl_up_sync(0xffffffffu, inc, off);
        if (lane >= off) inc += v;
    }
    if (lane == 31) ws[wid] = inc;
    __syncthreads();
    if (wid == 0) {
        int v = ws[lane];
        int winc = v;
        #pragma unroll
        for (int off = 1; off < 32; off <<= 1) {
            int u = __shfl_up_sync(0xffffffffu, winc, off);
            if (lane >= off) winc += u;
        }
        ws[lane] = winc - v;  // exclusive warp offset
    }
    __syncthreads();
    int off = ws[wid] + inc - s;  // exclusive thread offset
    #pragma unroll
    for (int j = 0; j < PER; j++) {
        int idx = base + j;
        if (idx < N_DST) {
            int e = off + loc[j];
            g_rowptr[idx] = e;
            g_cursor[idx] = e;
            g_counts[idx] = 0;   // restore invariant for next replay
        }
    }
    if (t == 1023) g_rowptr[N_DST] = off + s;
}

// ---------------------------------------------------------------------------
// 3) Scatter edges into CSR; restores g_flags to zero after reading.
// ---------------------------------------------------------------------------
__global__ void scatter_kernel(const int* __restrict__ edge_src,
                               const int* __restrict__ edge_dst) {
    int i = blockIdx.x * blockDim.x + threadIdx.x;
    if (i >= E_TOT / 4) return;
    int4 sv = ((const int4*)edge_src)[i];
    int4 dv = ((const int4*)edge_dst)[i];
    int fl = ((const int*)g_flags)[i];
    ((int*)g_flags)[i] = 0;              // restore invariant for next replay
    int p0 = atomicAdd(&g_cursor[dv.x - N_SRC], 1);
    g_packed[p0] = sv.x | ((fl & 1) << 31);
    int p1 = atomicAdd(&g_cursor[dv.y - N_SRC], 1);
    g_packed[p1] = sv.y | (((fl >> 8) & 1) << 31);
    int p2 = atomicAdd(&g_cursor[dv.z - N_SRC], 1);
    g_packed[p2] = sv.z | (((fl >> 16) & 1) << 31);
    int p3 = atomicAdd(&g_cursor[dv.w - N_SRC], 1);
    g_packed[p3] = sv.w | (((fl >> 24) & 1) << 31);
}

// ---------------------------------------------------------------------------
// 4) Aggregation with WARP-LEVEL WORK STEALING: persistent warps pull node
//    indices from a global cursor (removes intra-block degree-imbalance tail).
//    Per node: fused pos+neg shift-softmax, 4-deep register pipeline (proven
//    best), fused loss contribution.
// ---------------------------------------------------------------------------
#define AGG_LOAD(J, IDX)                                                     \
    {                                                                        \
        int _i = (IDX);                                                      \
        if (_i < pend) {                                                     \
            unsigned _u = (unsigned)g_packed[_i];                            \
            u##J = _u;                                                       \
            int _s = (int)(_u & 0x7fffffffu);                                \
            el##J = g_el[_s * NHEAD + h];                                    \
            z##J = *(const float4*)(g_z + (size_t)_s * FDIM + lane * 4);     \
        }                                                                    \
    }

#define AGG_PROC(J, IDX)                                                     \
    if ((IDX) < pend) {                                                      \
        float _e = el##J + er_h;                                             \
        _e = (_e >= 0.f) ? _e : NEG_SLOPE * _e;                              \
        float _w = __expf(_e - E_SHIFT);                                     \
        dP += _w;                                                            \
        aP.x += _w * z##J.x; aP.y += _w * z##J.y;                            \
        aP.z += _w * z##J.z; aP.w += _w * z##J.w;                            \
        if (u##J >> 31) {                                                    \
            dN += _w;                                                        \
            aN.x += _w * z##J.x; aN.y += _w * z##J.y;                        \
            aN.z += _w * z##J.z; aN.w += _w * z##J.w;                        \
        }                                                                    \
    }

__global__ void __launch_bounds__(256) aggregate_kernel(const float* __restrict__ bias,
                                                        const float* __restrict__ prelu_a,
                                                        float* __restrict__ out_pos) {
    const int lane = threadIdx.x & 31;
    const int h = lane >> 2;
    const float pa = prelu_a[0];
    const int f0 = lane * 4;
    const float b0 = bias[f0], b1 = bias[f0 + 1], b2 = bias[f0 + 2], b3 = bias[f0 + 3];

    while (true) {
        int i = 0;
        if (lane == 0) i = atomicAdd(&g_node_cursor, 1);
        i = __shfl_sync(0xffffffffu, i, 0);
        if (i >= N_DST) break;

        const int n = N_SRC + i;
        const float er_h = g_er[n * NHEAD + h];
        float4 zself = *(const float4*)(g_z + (size_t)n * FDIM + lane * 4);
        float e_self = g_el[n * NHEAD + h] + er_h;
        e_self = (e_self >= 0.f) ? e_self : NEG_SLOPE * e_self;
        float ws = __expf(e_self - E_SHIFT);

        float dP = ws, dN = ws;
        float4 aP = make_float4(ws * zself.x, ws * zself.y, ws * zself.z, ws * zself.w);
        float4 aN = aP;

        const int pbeg = g_rowptr[i], pend = g_rowptr[i + 1];

        unsigned u0 = 0, u1 = 0, u2 = 0, u3 = 0;
        float el0 = 0.f, el1 = 0.f, el2 = 0.f, el3 = 0.f;
        float4 z0 = {}, z1 = {}, z2 = {}, z3 = {};

        AGG_LOAD(0, pbeg + 0);
        AGG_LOAD(1, pbeg + 1);
        AGG_LOAD(2, pbeg + 2);
        AGG_LOAD(3, pbeg + 3);

        #pragma unroll 1
        for (int k = pbeg; k < pend; k += 4) {
            AGG_PROC(0, k + 0); AGG_LOAD(0, k + 4);
            AGG_PROC(1, k + 1); AGG_LOAD(1, k + 5);
            AGG_PROC(2, k + 2); AGG_LOAD(2, k + 6);
            AGG_PROC(3, k + 3); AGG_LOAD(3, k + 7);
        }

        float pv0, pv1, pv2, pv3, nv0, nv1, nv2, nv3;
        {   // positive
            float inv = 1.f / dP;
            float v0 = aP.x * inv + b0; v0 = (v0 >= 0.f) ? v0 : pa * v0;
            float v1 = aP.y * inv + b1; v1 = (v1 >= 0.f) ? v1 : pa * v1;
            float v2 = aP.z * inv + b2; v2 = (v2 >= 0.f) ? v2 : pa * v2;
            float v3 = aP.w * inv + b3; v3 = (v3 >= 0.f) ? v3 : pa * v3;
            #pragma unroll
            for (int off = 4; off <= 16; off <<= 1) {
                v0 += __shfl_xor_sync(0xffffffffu, v0, off);
                v1 += __shfl_xor_sync(0xffffffffu, v1, off);
                v2 += __shfl_xor_sync(0xffffffffu, v2, off);
                v3 += __shfl_xor_sync(0xffffffffu, v3, off);
            }
            pv0 = v0 * 0.125f; pv1 = v1 * 0.125f; pv2 = v2 * 0.125f; pv3 = v3 * 0.125f;
            if (lane < 4) {
                float* o = out_pos + (size_t)i * HDIM + lane * 4;
                o[0] = pv0; o[1] = pv1; o[2] = pv2; o[3] = pv3;
            }
        }
        {   // negative
            float inv = 1.f / dN;
            float v0 = aN.x * inv + b0; v0 = (v0 >= 0.f) ? v0 : pa * v0;
            float v1 = aN.y * inv + b1; v1 = (v1 >= 0.f) ? v1 : pa * v1;
            float v2 = aN.z * inv + b2; v2 = (v2 >= 0.f) ? v2 : pa * v2;
            float v3 = aN.w * inv + b3; v3 = (v3 >= 0.f) ? v3 : pa * v3;
            #pragma unroll
            for (int off = 4; off <= 16; off <<= 1) {
                v0 += __shfl_xor_sync(0xffffffffu, v0, off);
                v1 += __shfl_xor_sync(0xffffffffu, v1, off);
                v2 += __shfl_xor_sync(0xffffffffu, v2, off);
                v3 += __shfl_xor_sync(0xffffffffu, v3, off);
            }
            nv0 = v0 * 0.125f; nv1 = v1 * 0.125f; nv2 = v2 * 0.125f; nv3 = v3 * 0.125f;
        }

        // fused loss contribution
        float dot = pv0 * nv0 + pv1 * nv1 + pv2 * nv2 + pv3 * nv3;
        float na  = pv0 * pv0 + pv1 * pv1 + pv2 * pv2 + pv3 * pv3;
        float nb  = nv0 * nv0 + nv1 * nv1 + nv2 * nv2 + nv3 * nv3;
        dot += __shfl_xor_sync(0xffffffffu, dot, 1);
        dot += __shfl_xor_sync(0xffffffffu, dot, 2);
        na  += __shfl_xor_sync(0xffffffffu, na, 1);
        na  += __shfl_xor_sync(0xffffffffu, na, 2);
        nb  += __shfl_xor_sync(0xffffffffu, nb, 1);
        nb  += __shfl_xor_sync(0xffffffffu, nb, 2);
        if (lane == 0) {
            float den = fmaxf(sqrtf(na), 1e-8f) * fmaxf(sqrtf(nb), 1e-8f);
            atomicAdd(&g_loss, __expf(dot / den / TEM));
        }
    }
}

// ---------------------------------------------------------------------------
// 5) finalize: out[0] = log(sum); reset accumulators for the next replay.
// ---------------------------------------------------------------------------
__global__ void finalize_kernel(float* __restrict__ out) {
    out[0] = logf(g_loss);
    g_loss = 0.f;
    g_node_cursor = 0;
}

// ---------------------------------------------------------------------------
extern "C" void kernel_launch(void* const* d_in, const int* in_sizes, int n_in,
                              void* d_out, int out_size) {
    const float* feat    = (const float*)d_in[0];
    const float* fc_w    = (const float*)d_in[1];
    const float* attn_l  = (const float*)d_in[2];
    const float* attn_r  = (const float*)d_in[3];
    const float* bias    = (const float*)d_in[4];
    const float* prelu_a = (const float*)d_in[5];
    const int*   edge_src = (const int*)d_in[6];
    const int*   edge_dst = (const int*)d_in[7];
    const int*   neg_idx  = (const int*)d_in[8];
    const int    e_neg = in_sizes[8];

    float* out = (float*)d_out;          // [0] = loss, [1..] = h_pos (N_DST x 16)
    float* out_pos = out + 1;

    int fh_n = (e_neg > E_TOT / 4) ? e_neg : (E_TOT / 4);
    int hist_blocks = (fh_n + 255) / 256;

    bprep_kernel<<<32, 256>>>(fc_w);                                          // 0
    gemmhist_kernel<<<GEMM_BLOCKS + hist_blocks, 256>>>(feat, attn_l, attn_r,
                                                        neg_idx, e_neg, edge_dst); // 1
    scan_kernel<<<1, 1024>>>();                                               // 2
    scatter_kernel<<<(E_TOT / 4 + 255) / 256, 256>>>(edge_src, edge_dst);     // 3 (profiled)
    aggregate_kernel<<<1184, 256>>>(bias, prelu_a, out_pos);                  // 4
    finalize_kernel<<<1, 1>>>(out);                                           // 5
}

// round 17
// speedup vs baseline: 1.4178x; 1.0238x over previous
#include <cuda_runtime.h>
#include <cstdint>

// Problem constants (match reference)
#define N_SRC   20000
#define N_DST   20000
#define N_NODES 40000
#define E_TOT   320000
#define NHEAD   8
#define HDIM    16
#define FDIM    128
#define TEM     0.7f
#define NEG_SLOPE 0.2f
#define E_SHIFT 10.0f   // constant softmax shift; cancels in alpha = w / sum(w)

#define GEMM_BLOCKS 625   // (N_NODES/16 * 2 warps) * 32 / 256
#define BPREP_BLOCKS 32   // 16*16*32 / 256

// Scratch (device globals; zero-initialized at module load; every launch
// restores them to zero where required -> deterministic across graph replays)
__device__ float g_z[N_NODES * FDIM];        // 20.5 MB, L2-resident
__device__ float g_el[N_NODES * NHEAD];
__device__ float g_er[N_NODES * NHEAD];
__device__ int   g_counts[N_DST];            // zeroed by scan after reading
__device__ int   g_rowptr[N_DST + 1];
__device__ int   g_cursor[N_DST];
__device__ int   g_packed[E_TOT];            // src | (neg_flag << 31)
__device__ unsigned char g_flags[E_TOT];     // zeroed by scatter after reading
__device__ float g_hneg[N_DST * HDIM];
__device__ float g_loss;                     // zeroed by finalize after reading
__device__ int   g_node_cursor;              // work-stealing cursor; reset by finalize
// B fragments in mma lane order: [kstep 0..15][ntile 0..15][lane 0..31] = (b0hi,b1hi,b0lo,b1lo)
__device__ float4 g_bfrag[16 * 16 * 32];

__device__ __forceinline__ float tf32_hi(float x) {
    return __uint_as_float(__float_as_uint(x) & 0xFFFFE000u);
}

__device__ __forceinline__ void mma_tf32(float* d, unsigned a0, unsigned a1,
                                         unsigned a2, unsigned a3,
                                         unsigned b0, unsigned b1) {
    asm volatile(
        "mma.sync.aligned.m16n8k8.row.col.f32.tf32.tf32.f32 "
        "{%0,%1,%2,%3}, {%4,%5,%6,%7}, {%8,%9}, {%0,%1,%2,%3};\n"
        : "+f"(d[0]), "+f"(d[1]), "+f"(d[2]), "+f"(d[3])
        : "r"(a0), "r"(a1), "r"(a2), "r"(a3), "r"(b0), "r"(b1));
}

// ---------------------------------------------------------------------------
// 0) FUSED bprep + flags/hist (independent arrays -> safe overlap).
//    Blocks [0, BPREP_BLOCKS): swizzle fc_w into mma B-fragment order.
//    Blocks [BPREP_BLOCKS, ...): edge histogram + neg-flag marking.
// ---------------------------------------------------------------------------
__global__ void prep_hist_kernel(const float* __restrict__ fc_w,
                                 const int* __restrict__ neg_idx, int e_neg,
                                 const int* __restrict__ edge_dst) {
    if (blockIdx.x < BPREP_BLOCKS) {
        int i = blockIdx.x * blockDim.x + threadIdx.x;
        int lane = i & 31;
        int nt = (i >> 5) & 15;
        int ks = i >> 9;
        int k = ks * 8 + (lane & 3);       // threadID_in_group -> k row
        int n = nt * 8 + (lane >> 2);      // groupID -> n col
        float b0 = fc_w[k * FDIM + n];
        float b1 = fc_w[(k + 4) * FDIM + n];
        float b0h = tf32_hi(b0), b1h = tf32_hi(b1);
        g_bfrag[i] = make_float4(b0h, b1h, b0 - b0h, b1 - b1h);
        return;
    }
    int i = (blockIdx.x - BPREP_BLOCKS) * blockDim.x + threadIdx.x;
    if (i < E_TOT / 4) {
        int4 d = ((const int4*)edge_dst)[i];
        atomicAdd(&g_counts[d.x - N_SRC], 1);
        atomicAdd(&g_counts[d.y - N_SRC], 1);
        atomicAdd(&g_counts[d.z - N_SRC], 1);
        atomicAdd(&g_counts[d.w - N_SRC], 1);
    }
    if (i < e_neg) g_flags[neg_idx[i]] = 1;
}

// ---------------------------------------------------------------------------
// 1) Exclusive scan: single block, 1024 threads, 20 elems/thread, 2 barriers.
//    Restores g_counts to zero for the next replay.
// ---------------------------------------------------------------------------
__global__ void scan_kernel() {
    const int PER = 20;  // 1024*20 = 20480 >= N_DST
    __shared__ int ws[32];
    const int t = threadIdx.x;
    const int lane = t & 31, wid = t >> 5;
    const int base = t * PER;

    int loc[PER];
    int s = 0;
    #pragma unroll
    for (int j = 0; j < PER; j++) {
        int idx = base + j;
        int v = (idx < N_DST) ? g_counts[idx] : 0;
        loc[j] = s;
        s += v;
    }
    int inc = s;
    #pragma unroll
    for (int off = 1; off < 32; off <<= 1) {
        int v = __shfl_up_sync(0xffffffffu, inc, off);
        if (lane >= off) inc += v;
    }
    if (lane == 31) ws[wid] = inc;
    __syncthreads();
    if (wid == 0) {
        int v = ws[lane];
        int winc = v;
        #pragma unroll
        for (int off = 1; off < 32; off <<= 1) {
            int u = __shfl_up_sync(0xffffffffu, winc, off);
            if (lane >= off) winc += u;
        }
        ws[lane] = winc - v;  // exclusive warp offset
    }
    __syncthreads();
    int off = ws[wid] + inc - s;  // exclusive thread offset
    #pragma unroll
    for (int j = 0; j < PER; j++) {
        int idx = base + j;
        if (idx < N_DST) {
            int e = off + loc[j];
            g_rowptr[idx] = e;
            g_cursor[idx] = e;
            g_counts[idx] = 0;   // restore invariant for next replay
        }
    }
    if (t == 1023) g_rowptr[N_DST] = off + s;
}

// ---------------------------------------------------------------------------
// 2) FUSED gemm + scatter: blocks [0, GEMM_BLOCKS) run the tf32 gemm with
//    fused el/er epilogue (R7 config); remaining blocks scatter edges into the
//    CSR (latency-bound atomics hide under the gemm's tensor work).
// ---------------------------------------------------------------------------
__global__ void __launch_bounds__(256) gemmscatter_kernel(const float* __restrict__ feat,
                                                          const float* __restrict__ attn_l,
                                                          const float* __restrict__ attn_r,
                                                          const int* __restrict__ edge_src,
                                                          const int* __restrict__ edge_dst) {
    if (blockIdx.x >= GEMM_BLOCKS) {
        // ---- scatter part; restores g_flags to zero after reading ----
        int i = (blockIdx.x - GEMM_BLOCKS) * blockDim.x + threadIdx.x;
        if (i >= E_TOT / 4) return;
        int4 sv = ((const int4*)edge_src)[i];
        int4 dv = ((const int4*)edge_dst)[i];
        int fl = ((const int*)g_flags)[i];
        ((int*)g_flags)[i] = 0;              // restore invariant for next replay
        int p0 = atomicAdd(&g_cursor[dv.x - N_SRC], 1);
        g_packed[p0] = sv.x | ((fl & 1) << 31);
        int p1 = atomicAdd(&g_cursor[dv.y - N_SRC], 1);
        g_packed[p1] = sv.y | (((fl >> 8) & 1) << 31);
        int p2 = atomicAdd(&g_cursor[dv.z - N_SRC], 1);
        g_packed[p2] = sv.z | (((fl >> 16) & 1) << 31);
        int p3 = atomicAdd(&g_cursor[dv.w - N_SRC], 1);
        g_packed[p3] = sv.w | (((fl >> 24) & 1) << 31);
        return;
    }

    // ---- gemm part: one warp = 16 rows x 64 cols ----
    const int gw = (blockIdx.x * blockDim.x + threadIdx.x) >> 5;  // 0..4999
    const int row0 = (gw >> 1) * 16;
    const int ct = gw & 1;             // column half: cols [64*ct, 64*ct+64)
    const int lane = threadIdx.x & 31;
    const int g = lane >> 2;       // groupID (row within tile)
    const int tg = lane & 3;       // threadID_in_group

    const float* ar0 = feat + (size_t)(row0 + g) * FDIM;
    const float* ar1 = ar0 + 8 * FDIM;

    float acc[8][4];
    #pragma unroll
    for (int nt = 0; nt < 8; nt++) {
        acc[nt][0] = 0.f; acc[nt][1] = 0.f; acc[nt][2] = 0.f; acc[nt][3] = 0.f;
    }

    #pragma unroll 1
    for (int ks = 0; ks < 16; ks++) {
        float a0 = ar0[ks * 8 + tg];
        float a1 = ar1[ks * 8 + tg];
        float a2 = ar0[ks * 8 + tg + 4];
        float a3 = ar1[ks * 8 + tg + 4];
        unsigned h0 = __float_as_uint(a0) & 0xFFFFE000u;
        unsigned h1 = __float_as_uint(a1) & 0xFFFFE000u;
        unsigned h2 = __float_as_uint(a2) & 0xFFFFE000u;
        unsigned h3 = __float_as_uint(a3) & 0xFFFFE000u;
        unsigned l0 = __float_as_uint(a0 - __uint_as_float(h0));
        unsigned l1 = __float_as_uint(a1 - __uint_as_float(h1));
        unsigned l2 = __float_as_uint(a2 - __uint_as_float(h2));
        unsigned l3 = __float_as_uint(a3 - __uint_as_float(h3));

        const float4* bp = g_bfrag + ks * 16 * 32 + (ct * 8) * 32 + lane;
        #pragma unroll
        for (int nt = 0; nt < 8; nt++) {
            float4 b = bp[nt * 32];
            unsigned bx = __float_as_uint(b.x), by = __float_as_uint(b.y);
            unsigned bz = __float_as_uint(b.z), bw = __float_as_uint(b.w);
            mma_tf32(acc[nt], h0, h1, h2, h3, bx, by);   // hi * hi
            mma_tf32(acc[nt], l0, l1, l2, l3, bx, by);   // lo * hi
            mma_tf32(acc[nt], h0, h1, h2, h3, bz, bw);   // hi * lo
        }
    }

    // store z (this warp's column half)
    float* zr0 = g_z + (size_t)(row0 + g) * FDIM + ct * 64;
    float* zr1 = zr0 + 8 * FDIM;
    #pragma unroll
    for (int nt = 0; nt < 8; nt++) {
        *(float2*)(zr0 + nt * 8 + tg * 2) = make_float2(acc[nt][0], acc[nt][1]);
        *(float2*)(zr1 + nt * 8 + tg * 2) = make_float2(acc[nt][2], acc[nt][3]);
    }

    // fused el/er epilogue: this half holds heads h = ct*4 + hh, hh=0..3
    const int rA = (row0 + g) * NHEAD;
    const int rB = (row0 + g + 8) * NHEAD;
    #pragma unroll
    for (int hh = 0; hh < 4; hh++) {
        const int h = ct * 4 + hh;
        const int nt0 = 2 * hh, nt1 = 2 * hh + 1;
        const float* alp = attn_l + h * HDIM + tg * 2;
        const float* arp = attn_r + h * HDIM + tg * 2;
        float2 al0 = *(const float2*)(alp);
        float2 al1 = *(const float2*)(alp + 8);
        float2 arr0 = *(const float2*)(arp);
        float2 arr1 = *(const float2*)(arp + 8);
        float elA = acc[nt0][0] * al0.x + acc[nt0][1] * al0.y
                  + acc[nt1][0] * al1.x + acc[nt1][1] * al1.y;
        float elB = acc[nt0][2] * al0.x + acc[nt0][3] * al0.y
                  + acc[nt1][2] * al1.x + acc[nt1][3] * al1.y;
        float erA = acc[nt0][0] * arr0.x + acc[nt0][1] * arr0.y
                  + acc[nt1][0] * arr1.x + acc[nt1][1] * arr1.y;
        float erB = acc[nt0][2] * arr0.x + acc[nt0][3] * arr0.y
                  + acc[nt1][2] * arr1.x + acc[nt1][3] * arr1.y;
        elA += __shfl_xor_sync(0xffffffffu, elA, 1);
        elA += __shfl_xor_sync(0xffffffffu, elA, 2);
        elB += __shfl_xor_sync(0xffffffffu, elB, 1);
        elB += __shfl_xor_sync(0xffffffffu, elB, 2);
        erA += __shfl_xor_sync(0xffffffffu, erA, 1);
        erA += __shfl_xor_sync(0xffffffffu, erA, 2);
        erB += __shfl_xor_sync(0xffffffffu, erB, 1);
        erB += __shfl_xor_sync(0xffffffffu, erB, 2);
        if (tg == 0) {
            g_el[rA + h] = elA;
            g_el[rB + h] = elB;
            g_er[rA + h] = erA;
            g_er[rB + h] = erB;
        }
    }
}

// ---------------------------------------------------------------------------
// 3) Aggregation with warp-level work stealing: persistent warps pull node
//    indices from a global cursor. Per node: fused pos+neg shift-softmax,
//    4-deep register pipeline, fused loss contribution.   <-- PROFILED (idx 3)
// ---------------------------------------------------------------------------
#define AGG_LOAD(J, IDX)                                                     \
    {                                                                        \
        int _i = (IDX);                                                      \
        if (_i < pend) {                                                     \
            unsigned _u = (unsigned)g_packed[_i];                            \
            u##J = _u;                                                       \
            int _s = (int)(_u & 0x7fffffffu);                                \
            el##J = g_el[_s * NHEAD + h];                                    \
            z##J = *(const float4*)(g_z + (size_t)_s * FDIM + lane * 4);     \
        }                                                                    \
    }

#define AGG_PROC(J, IDX)                                                     \
    if ((IDX) < pend) {                                                      \
        float _e = el##J + er_h;                                             \
        _e = (_e >= 0.f) ? _e : NEG_SLOPE * _e;                              \
        float _w = __expf(_e - E_SHIFT);                                     \
        dP += _w;                                                            \
        aP.x += _w * z##J.x; aP.y += _w * z##J.y;                            \
        aP.z += _w * z##J.z; aP.w += _w * z##J.w;                            \
        if (u##J >> 31) {                                                    \
            dN += _w;                                                        \
            aN.x += _w * z##J.x; aN.y += _w * z##J.y;                        \
            aN.z += _w * z##J.z; aN.w += _w * z##J.w;                        \
        }                                                                    \
    }

__global__ void __launch_bounds__(256) aggregate_kernel(const float* __restrict__ bias,
                                                        const float* __restrict__ prelu_a,
                                                        float* __restrict__ out_pos) {
    const int lane = threadIdx.x & 31;
    const int h = lane >> 2;
    const float pa = prelu_a[0];
    const int f0 = lane * 4;
    const float b0 = bias[f0], b1 = bias[f0 + 1], b2 = bias[f0 + 2], b3 = bias[f0 + 3];

    while (true) {
        int i = 0;
        if (lane == 0) i = atomicAdd(&g_node_cursor, 1);
        i = __shfl_sync(0xffffffffu, i, 0);
        if (i >= N_DST) break;

        const int n = N_SRC + i;
        const float er_h = g_er[n * NHEAD + h];
        float4 zself = *(const float4*)(g_z + (size_t)n * FDIM + lane * 4);
        float e_self = g_el[n * NHEAD + h] + er_h;
        e_self = (e_self >= 0.f) ? e_self : NEG_SLOPE * e_self;
        float ws = __expf(e_self - E_SHIFT);

        float dP = ws, dN = ws;
        float4 aP = make_float4(ws * zself.x, ws * zself.y, ws * zself.z, ws * zself.w);
        float4 aN = aP;

        const int pbeg = g_rowptr[i], pend = g_rowptr[i + 1];

        unsigned u0 = 0, u1 = 0, u2 = 0, u3 = 0;
        float el0 = 0.f, el1 = 0.f, el2 = 0.f, el3 = 0.f;
        float4 z0 = {}, z1 = {}, z2 = {}, z3 = {};

        AGG_LOAD(0, pbeg + 0);
        AGG_LOAD(1, pbeg + 1);
        AGG_LOAD(2, pbeg + 2);
        AGG_LOAD(3, pbeg + 3);

        #pragma unroll 1
        for (int k = pbeg; k < pend; k += 4) {
            AGG_PROC(0, k + 0); AGG_LOAD(0, k + 4);
            AGG_PROC(1, k + 1); AGG_LOAD(1, k + 5);
            AGG_PROC(2, k + 2); AGG_LOAD(2, k + 6);
            AGG_PROC(3, k + 3); AGG_LOAD(3, k + 7);
        }

        float pv0, pv1, pv2, pv3, nv0, nv1, nv2, nv3;
        {   // positive
            float inv = 1.f / dP;
            float v0 = aP.x * inv + b0; v0 = (v0 >= 0.f) ? v0 : pa * v0;
            float v1 = aP.y * inv + b1; v1 = (v1 >= 0.f) ? v1 : pa * v1;
            float v2 = aP.z * inv + b2; v2 = (v2 >= 0.f) ? v2 : pa * v2;
            float v3 = aP.w * inv + b3; v3 = (v3 >= 0.f) ? v3 : pa * v3;
            #pragma unroll
            for (int off = 4; off <= 16; off <<= 1) {
                v0 += __shfl_xor_sync(0xffffffffu, v0, off);
                v1 += __shfl_xor_sync(0xffffffffu, v1, off);
                v2 += __shfl_xor_sync(0xffffffffu, v2, off);
                v3 += __shfl_xor_sync(0xffffffffu, v3, off);
            }
            pv0 = v0 * 0.125f; pv1 = v1 * 0.125f; pv2 = v2 * 0.125f; pv3 = v3 * 0.125f;
            if (lane < 4) {
                float* o = out_pos + (size_t)i * HDIM + lane * 4;
                o[0] = pv0; o[1] = pv1; o[2] = pv2; o[3] = pv3;
            }
        }
        {   // negative
            float inv = 1.f / dN;
            float v0 = aN.x * inv + b0; v0 = (v0 >= 0.f) ? v0 : pa * v0;
            float v1 = aN.y * inv + b1; v1 = (v1 >= 0.f) ? v1 : pa * v1;
            float v2 = aN.z * inv + b2; v2 = (v2 >= 0.f) ? v2 : pa * v2;
            float v3 = aN.w * inv + b3; v3 = (v3 >= 0.f) ? v3 : pa * v3;
            #pragma unroll
            for (int off = 4; off <= 16; off <<= 1) {
                v0 += __shfl_xor_sync(0xffffffffu, v0, off);
                v1 += __shfl_xor_sync(0xffffffffu, v1, off);
                v2 += __shfl_xor_sync(0xffffffffu, v2, off);
                v3 += __shfl_xor_sync(0xffffffffu, v3, off);
            }
            nv0 = v0 * 0.125f; nv1 = v1 * 0.125f; nv2 = v2 * 0.125f; nv3 = v3 * 0.125f;
        }

        // fused loss contribution
        float dot = pv0 * nv0 + pv1 * nv1 + pv2 * nv2 + pv3 * nv3;
        float na  = pv0 * pv0 + pv1 * pv1 + pv2 * pv2 + pv3 * pv3;
        float nb  = nv0 * nv0 + nv1 * nv1 + nv2 * nv2 + nv3 * nv3;
        dot += __shfl_xor_sync(0xffffffffu, dot, 1);
        dot += __shfl_xor_sync(0xffffffffu, dot, 2);
        na  += __shfl_xor_sync(0xffffffffu, na, 1);
        na  += __shfl_xor_sync(0xffffffffu, na, 2);
        nb  += __shfl_xor_sync(0xffffffffu, nb, 1);
        nb  += __shfl_xor_sync(0xffffffffu, nb, 2);
        if (lane == 0) {
            float den = fmaxf(sqrtf(na), 1e-8f) * fmaxf(sqrtf(nb), 1e-8f);
            atomicAdd(&g_loss, __expf(dot / den / TEM));
        }
    }
}

// ---------------------------------------------------------------------------
// 4) finalize: out[0] = log(sum); reset accumulators for the next replay.
// ---------------------------------------------------------------------------
__global__ void finalize_kernel(float* __restrict__ out) {
    out[0] = logf(g_loss);
    g_loss = 0.f;
    g_node_cursor = 0;
}

// ---------------------------------------------------------------------------
extern "C" void kernel_launch(void* const* d_in, const int* in_sizes, int n_in,
                              void* d_out, int out_size) {
    const float* feat    = (const float*)d_in[0];
    const float* fc_w    = (const float*)d_in[1];
    const float* attn_l  = (const float*)d_in[2];
    const float* attn_r  = (const float*)d_in[3];
    const float* bias    = (const float*)d_in[4];
    const float* prelu_a = (const float*)d_in[5];
    const int*   edge_src = (const int*)d_in[6];
    const int*   edge_dst = (const int*)d_in[7];
    const int*   neg_idx  = (const int*)d_in[8];
    const int    e_neg = in_sizes[8];

    float* out = (float*)d_out;          // [0] = loss, [1..] = h_pos (N_DST x 16)
    float* out_pos = out + 1;

    int fh_n = (e_neg > E_TOT / 4) ? e_neg : (E_TOT / 4);
    int hist_blocks = (fh_n + 255) / 256;
    int scat_blocks = (E_TOT / 4 + 255) / 256;

    prep_hist_kernel<<<BPREP_BLOCKS + hist_blocks, 256>>>(fc_w, neg_idx, e_neg, edge_dst); // 0
    scan_kernel<<<1, 1024>>>();                                                            // 1
    gemmscatter_kernel<<<GEMM_BLOCKS + scat_blocks, 256>>>(feat, attn_l, attn_r,
                                                           edge_src, edge_dst);            // 2
    aggregate_kernel<<<1184, 256>>>(bias, prelu_a, out_pos);                               // 3 (profiled)
    finalize_kernel<<<1, 1>>>(out);                                                        // 4
}